// round 1
// baseline (speedup 1.0000x reference)
#include <cuda_runtime.h>
#include <cstdint>

#define N_NODES 50000
#define N_EDGES 1600000
#define F 48
#define NREL 8

// nodes per block for transform
#define NT 64
#define NTP (NT + 4)   // padded row to avoid smem bank conflicts
#define TPB1 192
#define TPB2 256

// Per-(node,rel) transformed messages: 50000*8*48 floats = 76.8 MB (static device scratch)
__device__ float g_h2[(size_t)N_NODES * NREL * F];

// ---------------------------------------------------------------------------
// Kernel 1: h2[n,r,:] = relu(x[n] @ W1[r] + b1) @ W2[r]
// Block: one rel, 64 nodes. Thread: 4 nodes x 4 cols register tile.
// Inner loop = 1 LDS.128 (xT) + 1 LDS.128 (W row) per 16 FFMA.
// ---------------------------------------------------------------------------
__global__ __launch_bounds__(TPB1) void transform_kernel(
    const float* __restrict__ x, const float* __restrict__ W1,
    const float* __restrict__ W2, const float* __restrict__ b1)
{
    __shared__ __align__(16) float sW1[F * F];
    __shared__ __align__(16) float sW2[F * F];
    __shared__ __align__(16) float sXT[F][NTP];
    __shared__ __align__(16) float sH1T[F][NTP];

    const int r   = blockIdx.y;
    const int n0  = blockIdx.x * NT;
    const int tid = threadIdx.x;
    const int cg  = tid % 12;  // 12 col groups * 4 cols = 48
    const int ng  = tid / 12;  // 16 node groups * 4 nodes = 64

    // stage weights for this relation
    for (int i = tid; i < F * F; i += TPB1) {
        sW1[i] = W1[(size_t)r * F * F + i];
        sW2[i] = W2[(size_t)r * F * F + i];
    }
    // stage x, transposed: sXT[i][n]
    for (int idx = tid; idx < NT * F; idx += TPB1) {
        int n = idx / F, i = idx % F;
        int gn = n0 + n;
        sXT[i][n] = (gn < N_NODES) ? x[(size_t)gn * F + i] : 0.f;
    }
    __syncthreads();

    float acc[4][4];

    // -------- phase 1: h1 = relu(x @ W1 + b1) --------
    #pragma unroll
    for (int u = 0; u < 4; u++)
        #pragma unroll
        for (int c = 0; c < 4; c++) acc[u][c] = 0.f;

    #pragma unroll 8
    for (int i = 0; i < F; i++) {
        float4 xv = *reinterpret_cast<const float4*>(&sXT[i][ng * 4]);
        float4 wv = *reinterpret_cast<const float4*>(&sW1[i * F + cg * 4]);
        float xa[4] = {xv.x, xv.y, xv.z, xv.w};
        float wa[4] = {wv.x, wv.y, wv.z, wv.w};
        #pragma unroll
        for (int u = 0; u < 4; u++)
            #pragma unroll
            for (int c = 0; c < 4; c++)
                acc[u][c] += xa[u] * wa[c];
    }

    {
        float4 bv = *reinterpret_cast<const float4*>(&b1[cg * 4]);
        float ba[4] = {bv.x, bv.y, bv.z, bv.w};
        #pragma unroll
        for (int c = 0; c < 4; c++) {
            float4 hv;
            hv.x = fmaxf(acc[0][c] + ba[c], 0.f);
            hv.y = fmaxf(acc[1][c] + ba[c], 0.f);
            hv.z = fmaxf(acc[2][c] + ba[c], 0.f);
            hv.w = fmaxf(acc[3][c] + ba[c], 0.f);
            *reinterpret_cast<float4*>(&sH1T[cg * 4 + c][ng * 4]) = hv;
        }
    }
    __syncthreads();

    // -------- phase 2: h2 = h1 @ W2 --------
    #pragma unroll
    for (int u = 0; u < 4; u++)
        #pragma unroll
        for (int c = 0; c < 4; c++) acc[u][c] = 0.f;

    #pragma unroll 8
    for (int j = 0; j < F; j++) {
        float4 hv = *reinterpret_cast<const float4*>(&sH1T[j][ng * 4]);
        float4 wv = *reinterpret_cast<const float4*>(&sW2[j * F + cg * 4]);
        float ha[4] = {hv.x, hv.y, hv.z, hv.w};
        float wa[4] = {wv.x, wv.y, wv.z, wv.w};
        #pragma unroll
        for (int u = 0; u < 4; u++)
            #pragma unroll
            for (int c = 0; c < 4; c++)
                acc[u][c] += ha[u] * wa[c];
    }

    #pragma unroll
    for (int u = 0; u < 4; u++) {
        int gn = n0 + ng * 4 + u;
        if (gn < N_NODES) {
            *reinterpret_cast<float4*>(&g_h2[((size_t)gn * NREL + r) * F + cg * 4]) =
                make_float4(acc[u][0], acc[u][1], acc[u][2], acc[u][3]);
        }
    }
}

// ---------------------------------------------------------------------------
// Kernel 2: per-edge gather h2[src,rel] * norm, scatter-add into out[dst]
// Vectorized L2 atomics: red.global.add.v4.f32 (12 per edge instead of 48).
// ---------------------------------------------------------------------------
__global__ __launch_bounds__(TPB2) void edge_kernel(
    const int* __restrict__ src, const int* __restrict__ dst,
    const int* __restrict__ rel, const float* __restrict__ norm,
    float* __restrict__ out)
{
    int e = blockIdx.x * TPB2 + threadIdx.x;
    if (e >= N_EDGES) return;
    int s = src[e];
    int d = dst[e];
    int r = rel[e];
    float w = norm[e];

    const float4* h = reinterpret_cast<const float4*>(&g_h2[((size_t)s * NREL + r) * F]);
    float* o = out + (size_t)d * F;

    #pragma unroll
    for (int k = 0; k < F / 4; k++) {
        float4 v = h[k];
        asm volatile("red.global.add.v4.f32 [%0], {%1, %2, %3, %4};"
                     :: "l"(o + 4 * k),
                        "f"(v.x * w), "f"(v.y * w), "f"(v.z * w), "f"(v.w * w)
                     : "memory");
    }
}

// ---------------------------------------------------------------------------
// Kernel 3: out = relu(agg + bias2)
// ---------------------------------------------------------------------------
__global__ void finalize_kernel(float* __restrict__ out, const float* __restrict__ b2)
{
    int i = blockIdx.x * blockDim.x + threadIdx.x;
    if (i < N_NODES * F) {
        float v = out[i] + b2[i % F];
        out[i] = fmaxf(v, 0.f);
    }
}

// ---------------------------------------------------------------------------
extern "C" void kernel_launch(void* const* d_in, const int* in_sizes, int n_in,
                              void* d_out, int out_size)
{
    const float* x    = (const float*)d_in[0];
    const float* norm = (const float*)d_in[1];
    const float* W1   = (const float*)d_in[2];
    const float* W2   = (const float*)d_in[3];
    const float* b1   = (const float*)d_in[4];
    const float* b2   = (const float*)d_in[5];
    const int*   src  = (const int*)d_in[6];
    const int*   dst  = (const int*)d_in[7];
    const int*   rel  = (const int*)d_in[8];
    float* out = (float*)d_out;

    // output accumulates atomics; must be zeroed every replay
    cudaMemsetAsync(out, 0, (size_t)N_NODES * F * sizeof(float), 0);

    dim3 g1((N_NODES + NT - 1) / NT, NREL);
    transform_kernel<<<g1, TPB1>>>(x, W1, W2, b1);

    edge_kernel<<<(N_EDGES + TPB2 - 1) / TPB2, TPB2>>>(src, dst, rel, norm, out);

    finalize_kernel<<<(N_NODES * F + 255) / 256, 256>>>(out, b2);
}

// round 2
// speedup vs baseline: 1.2950x; 1.2950x over previous
#include <cuda_runtime.h>
#include <cstdint>

#define N_NODES 50000
#define N_EDGES 1600000
#define F 48
#define NREL 8

// nodes per block for transform
#define NT 64
#define NTP (NT + 4)   // padded row to avoid smem bank conflicts
#define TPB1 192
#define EPB 16         // edges per block in edge kernel (16*12 = 192 threads)
#define TPB2 192

// Per-(node,rel) transformed messages: 50000*8*48 floats = 76.8 MB (static device scratch)
__device__ float g_h2[(size_t)N_NODES * NREL * F];

// ---------------------------------------------------------------------------
// Kernel 1: h2[n,r,:] = relu(x[n] @ W1[r] + b1) @ W2[r]
// Block: one rel, 64 nodes. Thread: 4 nodes x 4 cols register tile.
// smem: sT buffer is reused for xT (phase 1) then h1T (phase 2) -> 31.5KB/block
// -> 7 blocks/SM -> 65% occupancy (was 44%).
// ---------------------------------------------------------------------------
__global__ __launch_bounds__(TPB1) void transform_kernel(
    const float* __restrict__ x, const float* __restrict__ W1,
    const float* __restrict__ W2, const float* __restrict__ b1)
{
    __shared__ __align__(16) float sW1[F * F];
    __shared__ __align__(16) float sW2[F * F];
    __shared__ __align__(16) float sT[F][NTP];   // xT, then h1T

    const int r   = blockIdx.y;
    const int n0  = blockIdx.x * NT;
    const int tid = threadIdx.x;
    const int cg  = tid % 12;  // 12 col groups * 4 cols = 48
    const int ng  = tid / 12;  // 16 node groups * 4 nodes = 64

    // stage weights for this relation
    #pragma unroll
    for (int i = tid; i < F * F; i += TPB1) {
        sW1[i] = W1[(size_t)r * F * F + i];
        sW2[i] = W2[(size_t)r * F * F + i];
    }
    // stage x, transposed: sT[i][n]
    #pragma unroll
    for (int idx = tid; idx < NT * F; idx += TPB1) {
        int n = idx / F, i = idx % F;
        int gn = n0 + n;
        sT[i][n] = (gn < N_NODES) ? x[(size_t)gn * F + i] : 0.f;
    }
    __syncthreads();

    float acc[4][4];

    // -------- phase 1: h1 = relu(x @ W1 + b1) --------
    #pragma unroll
    for (int u = 0; u < 4; u++)
        #pragma unroll
        for (int c = 0; c < 4; c++) acc[u][c] = 0.f;

    #pragma unroll 8
    for (int i = 0; i < F; i++) {
        float4 xv = *reinterpret_cast<const float4*>(&sT[i][ng * 4]);
        float4 wv = *reinterpret_cast<const float4*>(&sW1[i * F + cg * 4]);
        float xa[4] = {xv.x, xv.y, xv.z, xv.w};
        float wa[4] = {wv.x, wv.y, wv.z, wv.w};
        #pragma unroll
        for (int u = 0; u < 4; u++)
            #pragma unroll
            for (int c = 0; c < 4; c++)
                acc[u][c] += xa[u] * wa[c];
    }

    // everyone has finished READING sT (phase-1 operands live in acc regs now)
    __syncthreads();

    {
        float4 bv = *reinterpret_cast<const float4*>(&b1[cg * 4]);
        float ba[4] = {bv.x, bv.y, bv.z, bv.w};
        #pragma unroll
        for (int c = 0; c < 4; c++) {
            float4 hv;
            hv.x = fmaxf(acc[0][c] + ba[c], 0.f);
            hv.y = fmaxf(acc[1][c] + ba[c], 0.f);
            hv.z = fmaxf(acc[2][c] + ba[c], 0.f);
            hv.w = fmaxf(acc[3][c] + ba[c], 0.f);
            *reinterpret_cast<float4*>(&sT[cg * 4 + c][ng * 4]) = hv;
        }
    }
    __syncthreads();

    // -------- phase 2: h2 = h1 @ W2 --------
    #pragma unroll
    for (int u = 0; u < 4; u++)
        #pragma unroll
        for (int c = 0; c < 4; c++) acc[u][c] = 0.f;

    #pragma unroll 8
    for (int j = 0; j < F; j++) {
        float4 hv = *reinterpret_cast<const float4*>(&sT[j][ng * 4]);
        float4 wv = *reinterpret_cast<const float4*>(&sW2[j * F + cg * 4]);
        float ha[4] = {hv.x, hv.y, hv.z, hv.w};
        float wa[4] = {wv.x, wv.y, wv.z, wv.w};
        #pragma unroll
        for (int u = 0; u < 4; u++)
            #pragma unroll
            for (int c = 0; c < 4; c++)
                acc[u][c] += ha[u] * wa[c];
    }

    #pragma unroll
    for (int u = 0; u < 4; u++) {
        int gn = n0 + ng * 4 + u;
        if (gn < N_NODES) {
            *reinterpret_cast<float4*>(&g_h2[((size_t)gn * NREL + r) * F + cg * 4]) =
                make_float4(acc[u][0], acc[u][1], acc[u][2], acc[u][3]);
        }
    }
}

// ---------------------------------------------------------------------------
// Kernel 2: per-edge gather h2[src,rel] * norm, scatter-add into out[dst]
// Thread -> (edge, float4-slot): 12 consecutive lanes cover one edge's 192B
// row, so warp-level gather/RED addresses are contiguous runs (coalesced:
// ~4-6 L1tex wavefronts per warp instead of up to 384).
// ---------------------------------------------------------------------------
__global__ __launch_bounds__(TPB2) void edge_kernel(
    const int* __restrict__ src, const int* __restrict__ dst,
    const int* __restrict__ rel, const float* __restrict__ norm,
    float* __restrict__ out)
{
    const int tid = threadIdx.x;
    const int e = blockIdx.x * EPB + tid / 12;
    const int k = tid % 12;
    if (e >= N_EDGES) return;

    int s = __ldg(src + e);
    int d = __ldg(dst + e);
    int r = __ldg(rel + e);
    float w = __ldg(norm + e);

    float4 v = *reinterpret_cast<const float4*>(
        &g_h2[((size_t)s * NREL + r) * F + k * 4]);

    float* o = out + (size_t)d * F + k * 4;
    asm volatile("red.global.add.v4.f32 [%0], {%1, %2, %3, %4};"
                 :: "l"(o),
                    "f"(v.x * w), "f"(v.y * w), "f"(v.z * w), "f"(v.w * w)
                 : "memory");
}

// ---------------------------------------------------------------------------
// Kernel 3: out = relu(agg + bias2)
// ---------------------------------------------------------------------------
__global__ void finalize_kernel(float* __restrict__ out, const float* __restrict__ b2)
{
    int i = blockIdx.x * blockDim.x + threadIdx.x;
    if (i < N_NODES * F) {
        float v = out[i] + b2[i % F];
        out[i] = fmaxf(v, 0.f);
    }
}

// ---------------------------------------------------------------------------
extern "C" void kernel_launch(void* const* d_in, const int* in_sizes, int n_in,
                              void* d_out, int out_size)
{
    const float* x    = (const float*)d_in[0];
    const float* norm = (const float*)d_in[1];
    const float* W1   = (const float*)d_in[2];
    const float* W2   = (const float*)d_in[3];
    const float* b1   = (const float*)d_in[4];
    const float* b2   = (const float*)d_in[5];
    const int*   src  = (const int*)d_in[6];
    const int*   dst  = (const int*)d_in[7];
    const int*   rel  = (const int*)d_in[8];
    float* out = (float*)d_out;

    // output accumulates atomics; must be zeroed every replay
    cudaMemsetAsync(out, 0, (size_t)N_NODES * F * sizeof(float), 0);

    dim3 g1((N_NODES + NT - 1) / NT, NREL);
    transform_kernel<<<g1, TPB1>>>(x, W1, W2, b1);

    edge_kernel<<<(N_EDGES + EPB - 1) / EPB, TPB2>>>(src, dst, rel, norm, out);

    finalize_kernel<<<(N_NODES * F + 255) / 256, 256>>>(out, b2);
}